// round 10
// baseline (speedup 1.0000x reference)
#include <cuda_runtime.h>
#include <cstdint>

#define NN 13
#define HD 128
#define NLAYER 8
#define NJ 17
#define DMAX 33
#define OBSD 348
#define SPC 4                 // samples per CTA
#define MREAL (SPC*NN)        // 52 rows
#define XST 260               // xs row stride (floats), 16B-aligned rows
#define NTHREADS 384
#define NWARP 12
#define KTOT 256
#define KC 32
#define NCHUNK (KTOT/KC)      // 8
#define WCHUNK4 (KC*HD/4)     // 1024 float4 per chunk

__constant__ int c_feat[NN][DMAX] = {
  {0,1,2,3,4,22,23,24,25,26,27,45,46,47,48,49,50,51,52,53,54,175,176,177,178,179,180,270,271,272,273,274,275},
  {5,6,28,29,55,56,57,58,59,60,61,62,63,64,181,182,183,184,185,186,276,277,278,279,280,281,0,0,0,0,0,0,0},
  {7,30,65,66,67,68,69,70,71,72,73,74,187,188,189,190,191,192,253,254,255,282,283,284,285,286,287,0,0,0,0,0,0},
  {8,9,10,11,31,32,33,34,75,76,77,78,79,80,81,82,83,84,193,194,195,196,197,198,256,257,258,288,289,290,291,292,293},
  {11,34,85,86,87,88,89,90,91,92,93,94,199,200,201,202,203,204,259,294,295,296,297,298,299,0,0,0,0,0,0,0,0},
  {95,96,97,98,99,100,101,102,103,104,205,206,207,208,209,210,300,301,302,303,304,305,0,0,0,0,0,0,0,0,0,0,0},
  {12,13,14,15,35,36,37,38,105,106,107,108,109,110,111,112,113,114,211,212,213,214,215,216,260,261,262,306,307,308,309,310,311},
  {15,38,115,116,117,118,119,120,121,122,123,124,217,218,219,220,221,222,263,312,313,314,315,316,317,0,0,0,0,0,0,0,0},
  {125,126,127,128,129,130,131,132,133,134,223,224,225,226,227,228,318,319,320,321,322,323,0,0,0,0,0,0,0,0,0,0,0},
  {16,17,18,39,40,41,135,136,137,138,139,140,141,142,143,144,229,230,231,232,233,234,264,265,324,325,326,327,328,329,0,0,0},
  {18,41,145,146,147,148,149,150,151,152,153,154,235,236,237,238,239,240,266,330,331,332,333,334,335,0,0,0,0,0,0,0,0},
  {19,20,21,42,43,44,155,156,157,158,159,160,161,162,163,164,241,242,243,244,245,246,267,268,336,337,338,339,340,341,0,0,0},
  {21,44,165,166,167,168,169,170,171,172,173,174,247,248,249,250,251,252,269,342,343,344,345,346,347,0,0,0,0,0,0,0,0}
};
__constant__ int c_dcnt[NN] = {33,26,27,33,25,22,33,25,22,30,25,30,25};

__constant__ int c_nbr[NN][3] = {
  {1,9,11},{0,2,0},{1,3,6},{2,4,0},{3,5,0},{4,0,0},{2,7,0},
  {6,8,0},{7,0,0},{0,10,0},{9,0,0},{0,12,0},{11,0,0}
};
__constant__ int c_deg[NN] = {3,2,3,2,2,1,2,2,1,2,1,2,1};

__constant__ int c_jm0[NJ] = {1,1,1,2,2,2,3,2,2,2,6,0,0,9,0,0,11};
__constant__ int c_jm1[NJ] = {2,2,2,3,3,3,4,6,6,6,7,9,9,10,11,11,12};

__device__ __forceinline__ float eluf(float x) {
    return x > 0.0f ? x : expm1f(x);
}
__device__ __forceinline__ unsigned long long pk2(float lo, float hi) {
    unsigned long long r;
    asm("mov.b64 %0, {%1, %2};" : "=l"(r) : "f"(lo), "f"(hi));
    return r;
}
__device__ __forceinline__ void upk2(unsigned long long v, float& lo, float& hi) {
    asm("mov.b64 {%0, %1}, %2;" : "=f"(lo), "=f"(hi) : "l"(v));
}
// Blackwell packed dual-FP32 FMA (exact IEEE fp32 lanes)
__device__ __forceinline__ void fma2(unsigned long long& d, unsigned long long a, unsigned long long b) {
    asm("fma.rn.f32x2 %0, %1, %2, %0;" : "+l"(d) : "l"(a), "l"(b));
}

__global__ __launch_bounds__(NTHREADS, 2)
void gnn_kernel(const float* __restrict__ obs,
                const float* __restrict__ W1, const float* __restrict__ b1,
                const float* __restrict__ W2, const float* __restrict__ b2,
                const float* __restrict__ Wmsg, const float* __restrict__ bmsg,
                const float* __restrict__ Wout, const float* __restrict__ bout,
                float* __restrict__ out)
{
    extern __shared__ float sm[];
    float* xs = sm;                        // [52][260]: cols 0..127 = x, 128..255 = agg/h
    float* wb = sm + MREAL * XST;          // 2 x [32][128] weight ping-pong; head aliases obs buffer

    const int tid = threadIdx.x;
    const int base_s = blockIdx.x * SPC;

    const int tx = tid & 31;               // ull column pair: cols {tx, tx+32} (of 64)
    const int ty = tid >> 5;               // 0..11 row group / warp

    // ======== load obs tile (aliases wb buffer 0; dead before first weight store) ========
    float* obsb = wb;                      // [SPC][OBSD] = 1392 floats
    {
        const float4* g = (const float4*)(obs + (size_t)base_s * OBSD);
        float4* o4 = (float4*)obsb;
        for (int i = tid; i < SPC * OBSD / 4; i += NTHREADS) o4[i] = g[i];
    }
    __syncthreads();

    // ======== encoder phase 1: h = elu(gather(obs) @ W1[n] + b1[n]) -> xs agg cols ========
    for (int n = ty; n < NN; n += NWARP) {
        unsigned long long acc[SPC][2];
        {
            const unsigned long long* bp = (const unsigned long long*)(b1 + n * HD);
            unsigned long long b0 = bp[tx], b1v = bp[tx + 32];
            #pragma unroll
            for (int s = 0; s < SPC; ++s) { acc[s][0] = b0; acc[s][1] = b1v; }
        }
        const int dc = c_dcnt[n];
        #pragma unroll 1
        for (int d = 0; d < dc; ++d) {
            const int fi = c_feat[n][d];
            const unsigned long long* wr =
                (const unsigned long long*)(W1 + (n * DMAX + d) * HD);
            unsigned long long w0 = wr[tx], w1 = wr[tx + 32];
            #pragma unroll
            for (int s = 0; s < SPC; ++s) {
                float xe = obsb[s * OBSD + fi];
                unsigned long long p = pk2(xe, xe);
                fma2(acc[s][0], p, w0); fma2(acc[s][1], p, w1);
            }
        }
        #pragma unroll
        for (int s = 0; s < SPC; ++s) {
            float* dst = xs + (s * NN + n) * XST + HD;
            float lo, hi;
            upk2(acc[s][0], lo, hi);
            *(float2*)(dst + 2 * tx) = make_float2(eluf(lo), eluf(hi));
            upk2(acc[s][1], lo, hi);
            *(float2*)(dst + 2 * tx + 64) = make_float2(eluf(lo), eluf(hi));
        }
    }
    __syncthreads();

    // ======== encoder phase 2: x0 = h @ W2[n] + b2[n] -> xs x cols ========
    for (int n = ty; n < NN; n += NWARP) {
        unsigned long long acc[SPC][2];
        {
            const unsigned long long* bp = (const unsigned long long*)(b2 + n * HD);
            unsigned long long b0 = bp[tx], b1v = bp[tx + 32];
            #pragma unroll
            for (int s = 0; s < SPC; ++s) { acc[s][0] = b0; acc[s][1] = b1v; }
        }
        #pragma unroll 2
        for (int k = 0; k < HD; ++k) {
            const unsigned long long* wr =
                (const unsigned long long*)(W2 + (n * HD + k) * HD);
            unsigned long long w0 = wr[tx], w1 = wr[tx + 32];
            #pragma unroll
            for (int s = 0; s < SPC; ++s) {
                float xe = xs[(s * NN + n) * XST + HD + k];
                unsigned long long p = pk2(xe, xe);
                fma2(acc[s][0], p, w0); fma2(acc[s][1], p, w1);
            }
        }
        #pragma unroll
        for (int s = 0; s < SPC; ++s) {
            float* dst = xs + (s * NN + n) * XST;
            float lo, hi;
            upk2(acc[s][0], lo, hi);
            *(float2*)(dst + 2 * tx) = make_float2(lo, hi);
            upk2(acc[s][1], lo, hi);
            *(float2*)(dst + 2 * tx + 64) = make_float2(lo, hi);
        }
    }

    // Row tiling: ty<4 -> 5 rows (rows ty*5), ty>=4 -> 4 rows (20 + (ty-4)*4); total 52
    const int R = (ty < 4) ? 5 : 4;
    const int row0 = (ty < 4) ? ty * 5 : 20 + (ty - 4) * 4;
    int xoff[5];
    #pragma unroll
    for (int r = 0; r < 5; ++r) xoff[r] = (row0 + ((r < R) ? r : R - 1)) * XST;

    // ======== 8 message-passing layers ========
    for (int l = 0; l < NLAYER; ++l) {
        const float* Wl = Wmsg + (size_t)l * KTOT * HD;

        // prefetch weight chunk 0 into registers (LDG overlaps agg pass)
        float4 wreg[3];
        {
            const float4* g = (const float4*)Wl;
            #pragma unroll
            for (int r = 0; r < 3; ++r) {
                int i = tid + r * NTHREADS;
                if (i < WCHUNK4) wreg[r] = g[i];
            }
        }

        __syncthreads();   // encoder / previous writeback complete
        // aggregation: agg[s,n] = sum_{nb} x[s,nb]  (float4 over h)
        for (int i = tid; i < MREAL * (HD / 4); i += NTHREADS) {
            int h4 = i & 31;
            int m  = i >> 5;
            int n = m % NN;
            int s13 = m - n;
            float4 sum = *(const float4*)(xs + (s13 + c_nbr[n][0]) * XST + h4 * 4);
            int dg = c_deg[n];
            #pragma unroll
            for (int e = 1; e < 3; ++e)
                if (e < dg) {
                    float4 v = *(const float4*)(xs + (s13 + c_nbr[n][e]) * XST + h4 * 4);
                    sum.x += v.x; sum.y += v.y; sum.z += v.z; sum.w += v.w;
                }
            *(float4*)(xs + m * XST + HD + h4 * 4) = sum;
        }
        // store chunk 0 to ping buffer
        {
            float4* d4 = (float4*)wb;
            #pragma unroll
            for (int r = 0; r < 3; ++r) {
                int i = tid + r * NTHREADS;
                if (i < WCHUNK4) d4[i] = wreg[r];
            }
        }

        unsigned long long acc[5][2];
        {
            const unsigned long long* bp = (const unsigned long long*)(bmsg + l * HD);
            unsigned long long b0 = bp[tx], b1v = bp[tx + 32];
            #pragma unroll
            for (int r = 0; r < 5; ++r) { acc[r][0] = b0; acc[r][1] = b1v; }
        }

        for (int kc = 0; kc < NCHUNK; ++kc) {
            __syncthreads();   // current buffer staged; prior reads of next buffer done
            if (kc < NCHUNK - 1) {   // prefetch next chunk into registers
                const float4* g = (const float4*)(Wl + (kc + 1) * KC * HD);
                #pragma unroll
                for (int r = 0; r < 3; ++r) {
                    int i = tid + r * NTHREADS;
                    if (i < WCHUNK4) wreg[r] = g[i];
                }
            }
            const float* cur = wb + (kc & 1) * (KC * HD);
            const float* xk = xs + kc * KC;
            #pragma unroll 1
            for (int k4 = 0; k4 < KC; k4 += 4) {
                float4 a[5];
                #pragma unroll
                for (int r = 0; r < 5; ++r)
                    a[r] = *(const float4*)(xk + xoff[r] + k4);
                #pragma unroll
                for (int kk = 0; kk < 4; ++kk) {
                    const unsigned long long* wr =
                        (const unsigned long long*)(cur + kk * HD);
                    unsigned long long w0 = wr[tx], w1 = wr[tx + 32];
                    #pragma unroll
                    for (int r = 0; r < 5; ++r) {
                        const float* af = (const float*)&a[r];
                        float xe = af[kk];
                        unsigned long long p = pk2(xe, xe);
                        fma2(acc[r][0], p, w0);
                        fma2(acc[r][1], p, w1);
                    }
                }
                cur += 4 * HD;
            }
            if (kc < NCHUNK - 1) {   // store next chunk to pong buffer
                float4* d4 = (float4*)(wb + ((kc + 1) & 1) * (KC * HD));
                #pragma unroll
                for (int r = 0; r < 3; ++r) {
                    int i = tid + r * NTHREADS;
                    if (i < WCHUNK4) d4[i] = wreg[r];
                }
            }
        }
        __syncthreads();
        // ELU + writeback
        #pragma unroll
        for (int r = 0; r < 5; ++r) {
            if (r < R) {
                float* dst = xs + (row0 + r) * XST;
                float lo, hi;
                upk2(acc[r][0], lo, hi);
                *(float2*)(dst + 2 * tx) = make_float2(eluf(lo), eluf(hi));
                upk2(acc[r][1], lo, hi);
                *(float2*)(dst + 2 * tx + 64) = make_float2(eluf(lo), eluf(hi));
            }
        }
    }
    __syncthreads();

    // ======== joint readout ========
    const int lane = tid & 31;
    const int wrp = tid >> 5;
    for (int t = wrp; t < SPC * NJ; t += NWARP) {
        int s = t / NJ, j = t - s * NJ;
        const float* r0 = xs + (s * NN + c_jm0[j]) * XST;
        const float* r1 = xs + (s * NN + c_jm1[j]) * XST;
        const float* wj = Wout + j * 2 * HD;
        float4 x0 = *(const float4*)(r0 + lane * 4);
        float4 x1 = *(const float4*)(r1 + lane * 4);
        float4 w0 = *(const float4*)(wj + lane * 4);
        float4 w1 = *(const float4*)(wj + HD + lane * 4);
        float sum = x0.x*w0.x + x0.y*w0.y + x0.z*w0.z + x0.w*w0.w
                  + x1.x*w1.x + x1.y*w1.y + x1.z*w1.z + x1.w*w1.w;
        #pragma unroll
        for (int o = 16; o; o >>= 1)
            sum += __shfl_xor_sync(0xffffffffu, sum, o);
        if (lane == 0)
            out[(size_t)(base_s + s) * NJ + j] = sum + bout[j];
    }
}

extern "C" void kernel_launch(void* const* d_in, const int* in_sizes, int n_in,
                              void* d_out, int out_size) {
    const float* obs  = (const float*)d_in[0];
    const float* W1   = (const float*)d_in[1];
    const float* b1   = (const float*)d_in[2];
    const float* W2   = (const float*)d_in[3];
    const float* b2   = (const float*)d_in[4];
    const float* Wmsg = (const float*)d_in[5];
    const float* bmsg = (const float*)d_in[6];
    const float* Wout = (const float*)d_in[7];
    const float* bout = (const float*)d_in[8];
    float* out = (float*)d_out;

    int B = in_sizes[0] / OBSD;
    int nblk = B / SPC;                         // 4096
    size_t smem = (size_t)(MREAL * XST + 2 * KC * HD) * sizeof(float); // 86,848 B

    cudaFuncSetAttribute(gnn_kernel, cudaFuncAttributeMaxDynamicSharedMemorySize, (int)smem);
    gnn_kernel<<<nblk, NTHREADS, smem>>>(obs, W1, b1, W2, b2, Wmsg, bmsg, Wout, bout, out);
}

// round 11
// speedup vs baseline: 1.7339x; 1.7339x over previous
#include <cuda_runtime.h>
#include <cuda_bf16.h>
#include <cstdint>

#define NN 13
#define HD 128
#define NLAYER 8
#define NJ 17
#define DMAX 33
#define OBSD 348
#define SPC 8
#define MREAL 104
#define MPAD 128
#define XST 260
#define NTHREADS 512
#define CHUNK_U4 2048        // 4 k16-steps x 16 nt x 32 lanes (uint4) = 32KB

// fragment-packed bf16 hi/lo W images: per layer 16 k16 x 16 nt x 32 lanes x uint4
__device__ __align__(16) uint4 g_Bfrag[NLAYER][16 * 16 * 32];

__constant__ int c_feat[NN][DMAX] = {
  {0,1,2,3,4,22,23,24,25,26,27,45,46,47,48,49,50,51,52,53,54,175,176,177,178,179,180,270,271,272,273,274,275},
  {5,6,28,29,55,56,57,58,59,60,61,62,63,64,181,182,183,184,185,186,276,277,278,279,280,281,0,0,0,0,0,0,0},
  {7,30,65,66,67,68,69,70,71,72,73,74,187,188,189,190,191,192,253,254,255,282,283,284,285,286,287,0,0,0,0,0,0},
  {8,9,10,11,31,32,33,34,75,76,77,78,79,80,81,82,83,84,193,194,195,196,197,198,256,257,258,288,289,290,291,292,293},
  {11,34,85,86,87,88,89,90,91,92,93,94,199,200,201,202,203,204,259,294,295,296,297,298,299,0,0,0,0,0,0,0,0},
  {95,96,97,98,99,100,101,102,103,104,205,206,207,208,209,210,300,301,302,303,304,305,0,0,0,0,0,0,0,0,0,0,0},
  {12,13,14,15,35,36,37,38,105,106,107,108,109,110,111,112,113,114,211,212,213,214,215,216,260,261,262,306,307,308,309,310,311},
  {15,38,115,116,117,118,119,120,121,122,123,124,217,218,219,220,221,222,263,312,313,314,315,316,317,0,0,0,0,0,0,0,0},
  {125,126,127,128,129,130,131,132,133,134,223,224,225,226,227,228,318,319,320,321,322,323,0,0,0,0,0,0,0,0,0,0,0},
  {16,17,18,39,40,41,135,136,137,138,139,140,141,142,143,144,229,230,231,232,233,234,264,265,324,325,326,327,328,329,0,0,0},
  {18,41,145,146,147,148,149,150,151,152,153,154,235,236,237,238,239,240,266,330,331,332,333,334,335,0,0,0,0,0,0,0,0},
  {19,20,21,42,43,44,155,156,157,158,159,160,161,162,163,164,241,242,243,244,245,246,267,268,336,337,338,339,340,341,0,0,0},
  {21,44,165,166,167,168,169,170,171,172,173,174,247,248,249,250,251,252,269,342,343,344,345,346,347,0,0,0,0,0,0,0,0}
};
__constant__ int c_dcnt[NN] = {33,26,27,33,25,22,33,25,22,30,25,30,25};
__constant__ int c_nbr[NN][3] = {
  {1,9,11},{0,2,0},{1,3,6},{2,4,0},{3,5,0},{4,0,0},{2,7,0},
  {6,8,0},{7,0,0},{0,10,0},{9,0,0},{0,12,0},{11,0,0}
};
__constant__ int c_deg[NN] = {3,2,3,2,2,1,2,2,1,2,1,2,1};
__constant__ int c_jm0[NJ] = {1,1,1,2,2,2,3,2,2,2,6,0,0,9,0,0,11};
__constant__ int c_jm1[NJ] = {2,2,2,3,3,3,4,6,6,6,7,9,9,10,11,11,12};

__device__ __forceinline__ float eluf(float x) { return x > 0.0f ? x : expm1f(x); }
__device__ __forceinline__ unsigned long long pk2(float lo, float hi) {
    unsigned long long r;
    asm("mov.b64 %0, {%1, %2};" : "=l"(r) : "f"(lo), "f"(hi));
    return r;
}
__device__ __forceinline__ void upk2(unsigned long long v, float& lo, float& hi) {
    asm("mov.b64 {%0, %1}, %2;" : "=f"(lo), "=f"(hi) : "l"(v));
}
__device__ __forceinline__ void fma2(unsigned long long& d, unsigned long long a, unsigned long long b) {
    asm("fma.rn.f32x2 %0, %1, %2, %0;" : "+l"(d) : "l"(a), "l"(b));
}

// d = {lo16 = bf16(b), hi16 = bf16(a)}  (PTX cvt packs %1 into high, %2 into low)
__device__ __forceinline__ uint32_t cvt_bf16x2(float hi, float lo) {
    uint32_t r;
    asm("cvt.rn.bf16x2.f32 %0, %1, %2;" : "=r"(r) : "f"(hi), "f"(lo));
    return r;
}
// split float2 (f.x = element k, f.y = element k+1) into hi (truncated) + lo (residual)
__device__ __forceinline__ void split_pair(float2 f, uint32_t& hi, uint32_t& lo) {
    uint32_t u0 = __float_as_uint(f.x), u1 = __float_as_uint(f.y);
    hi = __byte_perm(u0, u1, 0x7632);                 // {bf_trunc(f.x) | bf_trunc(f.y)<<16}
    float r0 = f.x - __uint_as_float(u0 & 0xFFFF0000u);
    float r1 = f.y - __uint_as_float(u1 & 0xFFFF0000u);
    lo = cvt_bf16x2(r1, r0);
}
__device__ __forceinline__ void mma_bf16(float* c, const uint32_t* a, uint32_t b0, uint32_t b1) {
    asm("mma.sync.aligned.m16n8k16.row.col.f32.bf16.bf16.f32 "
        "{%0,%1,%2,%3}, {%4,%5,%6,%7}, {%8,%9}, {%0,%1,%2,%3};"
        : "+f"(c[0]), "+f"(c[1]), "+f"(c[2]), "+f"(c[3])
        : "r"(a[0]), "r"(a[1]), "r"(a[2]), "r"(a[3]), "r"(b0), "r"(b1));
}

// ======== prep: build fragment-packed bf16 hi/lo W images ========
__global__ void prep_kernel(const float* __restrict__ Wmsg) {
    int idx = blockIdx.x * 256 + threadIdx.x;     // [0, 8*16*16*32)
    int lane = idx & 31;
    int nt   = (idx >> 5) & 15;
    int k16  = (idx >> 9) & 15;
    int l    = idx >> 13;
    if (l >= NLAYER) return;
    int n  = nt * 8 + (lane >> 2);
    int q2 = (lane & 3) * 2;
    int kb = k16 * 16;
    const float* W = Wmsg + (size_t)l * 256 * HD;
    float w0 = W[(kb + q2) * HD + n];
    float w1 = W[(kb + q2 + 1) * HD + n];
    float w2 = W[(kb + 8 + q2) * HD + n];
    float w3 = W[(kb + 8 + q2 + 1) * HD + n];
    // hi = rn(bf16), lo = rn(residual)
    __nv_bfloat162 h0 = __floats2bfloat162_rn(w0, w1);   // .x = w0 (low half)
    __nv_bfloat162 h1 = __floats2bfloat162_rn(w2, w3);
    __nv_bfloat162 l0 = __floats2bfloat162_rn(w0 - __bfloat162float(h0.x),
                                              w1 - __bfloat162float(h0.y));
    __nv_bfloat162 l1 = __floats2bfloat162_rn(w2 - __bfloat162float(h1.x),
                                              w3 - __bfloat162float(h1.y));
    uint4 v;
    v.x = *reinterpret_cast<uint32_t*>(&h0);
    v.y = *reinterpret_cast<uint32_t*>(&h1);
    v.z = *reinterpret_cast<uint32_t*>(&l0);
    v.w = *reinterpret_cast<uint32_t*>(&l1);
    g_Bfrag[l][(k16 * 16 + nt) * 32 + lane] = v;
}

// ======== main kernel ========
__global__ __launch_bounds__(NTHREADS)
void gnn_mma_kernel(const float* __restrict__ obs,
                    const float* __restrict__ W1, const float* __restrict__ b1,
                    const float* __restrict__ W2, const float* __restrict__ b2,
                    const float* __restrict__ Wmsg, const float* __restrict__ bmsg,
                    const float* __restrict__ Wout, const float* __restrict__ bout,
                    float* __restrict__ out)
{
    extern __shared__ float sm[];
    float* xs = sm;                                 // [128][260] fp32: cols 0..127 x, 128..255 agg/h
    uint4* wb4 = (uint4*)(sm + MPAD * XST);         // 2 x 2048 uint4 = 64KB ping-pong
    float* sbias = sm + MPAD * XST + 4 * CHUNK_U4 * 2; // 1024 floats (uint4 = 4 floats)

    const int tid  = threadIdx.x;
    const int lane = tid & 31;
    const int ty   = tid >> 5;                      // warp 0..15
    const int base_s = blockIdx.x * SPC;

    // ======== load obs (aliases wb region) + bias table ========
    float* obsb = (float*)wb4;                      // 8*348 = 2784 floats < 16K
    {
        const float4* g = (const float4*)(obs + (size_t)base_s * OBSD);
        float4* o4 = (float4*)obsb;
        for (int i = tid; i < SPC * OBSD / 4; i += NTHREADS) o4[i] = g[i];
        if (tid < 256) ((float4*)sbias)[tid] = ((const float4*)bmsg)[tid];
    }
    __syncthreads();

    // ======== encoder (fp32 FFMA2, warp = node) ========
    const int tx = lane;
    if (ty < NN) {
        const int n = ty;
        unsigned long long acc[SPC][2];
        {
            const unsigned long long* bp = (const unsigned long long*)(b1 + n * HD);
            unsigned long long a0 = bp[tx], a1 = bp[tx + 32];
            #pragma unroll
            for (int s = 0; s < SPC; ++s) { acc[s][0] = a0; acc[s][1] = a1; }
        }
        const int dc = c_dcnt[n];
        #pragma unroll 1
        for (int d = 0; d < dc; ++d) {
            const int fi = c_feat[n][d];
            const unsigned long long* wr = (const unsigned long long*)(W1 + (n * DMAX + d) * HD);
            unsigned long long w0 = wr[tx], w1 = wr[tx + 32];
            #pragma unroll
            for (int s = 0; s < SPC; ++s) {
                float xe = obsb[s * OBSD + fi];
                unsigned long long p = pk2(xe, xe);
                fma2(acc[s][0], p, w0); fma2(acc[s][1], p, w1);
            }
        }
        #pragma unroll
        for (int s = 0; s < SPC; ++s) {
            float* dst = xs + (s * NN + n) * XST + HD;
            float lo, hi;
            upk2(acc[s][0], lo, hi);
            *(float2*)(dst + 2 * tx) = make_float2(eluf(lo), eluf(hi));
            upk2(acc[s][1], lo, hi);
            *(float2*)(dst + 2 * tx + 64) = make_float2(eluf(lo), eluf(hi));
        }
    }
    __syncthreads();
    if (ty < NN) {
        const int n = ty;
        unsigned long long acc[SPC][2];
        {
            const unsigned long long* bp = (const unsigned long long*)(b2 + n * HD);
            unsigned long long a0 = bp[tx], a1 = bp[tx + 32];
            #pragma unroll
            for (int s = 0; s < SPC; ++s) { acc[s][0] = a0; acc[s][1] = a1; }
        }
        #pragma unroll 2
        for (int k = 0; k < HD; ++k) {
            const unsigned long long* wr = (const unsigned long long*)(W2 + (n * HD + k) * HD);
            unsigned long long w0 = wr[tx], w1 = wr[tx + 32];
            #pragma unroll
            for (int s = 0; s < SPC; ++s) {
                float xe = xs[(s * NN + n) * XST + HD + k];
                unsigned long long p = pk2(xe, xe);
                fma2(acc[s][0], p, w0); fma2(acc[s][1], p, w1);
            }
        }
        #pragma unroll
        for (int s = 0; s < SPC; ++s) {
            float* dst = xs + (s * NN + n) * XST;
            float lo, hi;
            upk2(acc[s][0], lo, hi);
            *(float2*)(dst + 2 * tx) = make_float2(lo, hi);
            upk2(acc[s][1], lo, hi);
            *(float2*)(dst + 2 * tx + 64) = make_float2(lo, hi);
        }
    }
    __syncthreads();
    // zero pad rows 104..127 (all 260 cols; 24*260 floats, 16B-aligned start)
    {
        float4* p4 = (float4*)(xs + MREAL * XST);
        for (int i = tid; i < 24 * XST / 4; i += NTHREADS)
            p4[i] = make_float4(0.f, 0.f, 0.f, 0.f);
    }

    // GEMM warp tiling: 4 m-groups x 4 n-groups
    const int mwarp = ty >> 2;
    const int nwarp = ty & 3;
    const int qr = lane >> 2;            // lane/4
    const int q2 = (lane & 3) * 2;       // 2*(lane%4)

    // ======== 8 message-passing layers ========
    for (int l = 0; l < NLAYER; ++l) {
        const uint4* Bl = g_Bfrag[l];

        // prefetch chunk 0 (LDG overlaps agg pass)
        uint4 wreg[4];
        #pragma unroll
        for (int r = 0; r < 4; ++r) wreg[r] = Bl[tid + r * NTHREADS];

        __syncthreads();   // encoder / previous epilogue complete
        // aggregation pass: agg cols from x cols
        for (int i = tid; i < MREAL * (HD / 4); i += NTHREADS) {
            int h4 = i & 31;
            int m  = i >> 5;
            int n = m % NN;
            int s13 = m - n;
            float4 sum = *(const float4*)(xs + (s13 + c_nbr[n][0]) * XST + h4 * 4);
            int dg = c_deg[n];
            #pragma unroll
            for (int e = 1; e < 3; ++e)
                if (e < dg) {
                    float4 v = *(const float4*)(xs + (s13 + c_nbr[n][e]) * XST + h4 * 4);
                    sum.x += v.x; sum.y += v.y; sum.z += v.z; sum.w += v.w;
                }
            *(float4*)(xs + m * XST + HD + h4 * 4) = sum;
        }
        // store chunk 0
        #pragma unroll
        for (int r = 0; r < 4; ++r) wb4[tid + r * NTHREADS] = wreg[r];

        float C[2][4][4];
        #pragma unroll
        for (int t = 0; t < 2; ++t)
            #pragma unroll
            for (int nt = 0; nt < 4; ++nt)
                #pragma unroll
                for (int e = 0; e < 4; ++e) C[t][nt][e] = 0.0f;

        for (int kc = 0; kc < 4; ++kc) {
            __syncthreads();
            if (kc < 3) {
                #pragma unroll
                for (int r = 0; r < 4; ++r)
                    wreg[r] = Bl[(kc + 1) * CHUNK_U4 + tid + r * NTHREADS];
            }
            const uint4* cur = wb4 + (kc & 1) * CHUNK_U4;
            #pragma unroll
            for (int k16 = 0; k16 < 4; ++k16) {
                const int kb = kc * 64 + k16 * 16;
                // build A fragments (2 m-tiles), hi + lo
                uint32_t Ah[2][4], Al[2][4];
                #pragma unroll
                for (int t = 0; t < 2; ++t) {
                    const float* xr = xs + (mwarp * 32 + t * 16 + qr) * XST + kb;
                    float2 p0 = *(const float2*)(xr + q2);
                    float2 p1 = *(const float2*)(xr + 8 * XST + q2);
                    float2 p2 = *(const float2*)(xr + q2 + 8);
                    float2 p3 = *(const float2*)(xr + 8 * XST + q2 + 8);
                    split_pair(p0, Ah[t][0], Al[t][0]);
                    split_pair(p1, Ah[t][1], Al[t][1]);
                    split_pair(p2, Ah[t][2], Al[t][2]);
                    split_pair(p3, Ah[t][3], Al[t][3]);
                }
                // B fragments + 3-pass MMA
                #pragma unroll
                for (int nt = 0; nt < 4; ++nt) {
                    uint4 bv = cur[(k16 * 16 + nwarp * 4 + nt) * 32 + lane];
                    #pragma unroll
                    for (int t = 0; t < 2; ++t) {
                        mma_bf16(C[t][nt], Ah[t], bv.x, bv.y);   // Ah * Bh
                        mma_bf16(C[t][nt], Al[t], bv.x, bv.y);   // Al * Bh
                        mma_bf16(C[t][nt], Ah[t], bv.z, bv.w);   // Ah * Bl
                    }
                }
            }
            if (kc < 3) {
                uint4* d4 = wb4 + ((kc + 1) & 1) * CHUNK_U4;
                #pragma unroll
                for (int r = 0; r < 4; ++r) d4[tid + r * NTHREADS] = wreg[r];
            }
        }
        __syncthreads();
        // epilogue: x = elu(C + bias) -> xs x cols
        #pragma unroll
        for (int t = 0; t < 2; ++t) {
            const int r0 = mwarp * 32 + t * 16 + qr;
            #pragma unroll
            for (int nt = 0; nt < 4; ++nt) {
                const int col = nwarp * 32 + nt * 8 + q2;
                float2 bb = *(const float2*)(sbias + l * HD + col);
                if (r0 < MREAL) {
                    *(float2*)(xs + r0 * XST + col) =
                        make_float2(eluf(C[t][nt][0] + bb.x), eluf(C[t][nt][1] + bb.y));
                }
                if (r0 + 8 < MREAL) {
                    *(float2*)(xs + (r0 + 8) * XST + col) =
                        make_float2(eluf(C[t][nt][2] + bb.x), eluf(C[t][nt][3] + bb.y));
                }
            }
        }
    }
    __syncthreads();

    // ======== joint readout ========
    for (int t = ty; t < SPC * NJ; t += 16) {
        int s = t / NJ, j = t - s * NJ;
        const float* r0 = xs + (s * NN + c_jm0[j]) * XST;
        const float* r1 = xs + (s * NN + c_jm1[j]) * XST;
        const float* wj = Wout + j * 2 * HD;
        float4 x0 = *(const float4*)(r0 + lane * 4);
        float4 x1 = *(const float4*)(r1 + lane * 4);
        float4 w0 = *(const float4*)(wj + lane * 4);
        float4 w1 = *(const float4*)(wj + HD + lane * 4);
        float sum = x0.x*w0.x + x0.y*w0.y + x0.z*w0.z + x0.w*w0.w
                  + x1.x*w1.x + x1.y*w1.y + x1.z*w1.z + x1.w*w1.w;
        #pragma unroll
        for (int o = 16; o; o >>= 1)
            sum += __shfl_xor_sync(0xffffffffu, sum, o);
        if (lane == 0)
            out[(size_t)(base_s + s) * NJ + j] = sum + bout[j];
    }
}

extern "C" void kernel_launch(void* const* d_in, const int* in_sizes, int n_in,
                              void* d_out, int out_size) {
    const float* obs  = (const float*)d_in[0];
    const float* W1   = (const float*)d_in[1];
    const float* b1   = (const float*)d_in[2];
    const float* W2   = (const float*)d_in[3];
    const float* b2   = (const float*)d_in[4];
    const float* Wmsg = (const float*)d_in[5];
    const float* bmsg = (const float*)d_in[6];
    const float* Wout = (const float*)d_in[7];
    const float* bout = (const float*)d_in[8];
    float* out = (float*)d_out;

    prep_kernel<<<NLAYER * 16 * 16 * 32 / 256, 256>>>(Wmsg);

    int B = in_sizes[0] / OBSD;
    int nblk = B / SPC;                         // 2048
    // xs 128*260*4 + wb 64KB + sbias 4KB = 202,752 B
    size_t smem = (size_t)(MPAD * XST + 8 * CHUNK_U4 + 1024) * sizeof(float);
    cudaFuncSetAttribute(gnn_mma_kernel, cudaFuncAttributeMaxDynamicSharedMemorySize, (int)smem);
    gnn_mma_kernel<<<nblk, NTHREADS, smem>>>(obs, W1, b1, W2, b2, Wmsg, bmsg, Wout, bout, out);
}